// round 2
// baseline (speedup 1.0000x reference)
#include <cuda_runtime.h>
#include <cuda_bf16.h>
#include <cstddef>

// Problem shapes (fixed by setup_inputs): F=2, B=64, S=512, D=768
#define Fdim  2
#define Bdim  64
#define FB    (Fdim * Bdim)      // 128
#define Sdim  512
#define Ddim  768
#define D4    (Ddim / 4)         // 192 float4 per row
#define SPLIT 8                  // S-splits per (f,b)
#define RPB   (Sdim / SPLIT)     // 64 rows per block
#define NBLK  (FB * SPLIT)       // 1024 blocks

#define EPSV  1e-9f

// Deterministic scratch (no device-side allocation allowed)
__device__ float g_partial[NBLK];

// ---------------------------------------------------------------------------
// Kernel 1: per-block partial of T_fb = sum_s mask[s] * dot(tok[s,:], sent)
// 192 threads == D4 lanes; each thread owns one float4 column slice.
// Masked-out rows are skipped entirely (saves ~50% of HBM traffic).
// ---------------------------------------------------------------------------
__global__ __launch_bounds__(192, 8)
void noun_dot_kernel(const float4* __restrict__ tok,
                     const float4* __restrict__ sent,
                     const int*    __restrict__ mask)
{
    const int fb  = blockIdx.x >> 3;        // / SPLIT
    const int sp  = blockIdx.x & (SPLIT - 1);
    const int tid = threadIdx.x;            // 0..191

    __shared__ float4 s_sent[D4];
    __shared__ int    s_mask[RPB];

    s_sent[tid] = sent[(size_t)fb * D4 + tid];
    if (tid < RPB)
        s_mask[tid] = mask[fb * Sdim + sp * RPB + tid];
    __syncthreads();

    // Hoist the 64 mask bits into two registers: predicate compute is then
    // pure ALU (no LDS on the load-issue critical path).
    unsigned mlo = 0u, mhi = 0u;
    #pragma unroll
    for (int i = 0; i < 32; i++) {
        mlo |= (s_mask[i]      ? 1u : 0u) << i;
        mhi |= (s_mask[i + 32] ? 1u : 0u) << i;
    }

    const float4 w = s_sent[tid];           // register-resident weight slice
    const float4* base = tok + ((size_t)fb * Sdim + (size_t)sp * RPB) * D4 + tid;

    float a0 = 0.f, a1 = 0.f, a2 = 0.f, a3 = 0.f;
    #pragma unroll 2
    for (int r = 0; r < RPB; r += 4) {
        const unsigned mw = (r < 32) ? mlo : mhi;
        const int      sh = r & 31;
        // 4 independent predicated rows -> 4 LDG.128 in flight, 4 FMA chains
        if ((mw >> (sh + 0)) & 1u) {
            float4 t = base[(size_t)(r + 0) * D4];
            a0 = fmaf(t.x, w.x, a0); a0 = fmaf(t.y, w.y, a0);
            a0 = fmaf(t.z, w.z, a0); a0 = fmaf(t.w, w.w, a0);
        }
        if ((mw >> (sh + 1)) & 1u) {
            float4 t = base[(size_t)(r + 1) * D4];
            a1 = fmaf(t.x, w.x, a1); a1 = fmaf(t.y, w.y, a1);
            a1 = fmaf(t.z, w.z, a1); a1 = fmaf(t.w, w.w, a1);
        }
        if ((mw >> (sh + 2)) & 1u) {
            float4 t = base[(size_t)(r + 2) * D4];
            a2 = fmaf(t.x, w.x, a2); a2 = fmaf(t.y, w.y, a2);
            a2 = fmaf(t.z, w.z, a2); a2 = fmaf(t.w, w.w, a2);
        }
        if ((mw >> (sh + 3)) & 1u) {
            float4 t = base[(size_t)(r + 3) * D4];
            a3 = fmaf(t.x, w.x, a3); a3 = fmaf(t.y, w.y, a3);
            a3 = fmaf(t.z, w.z, a3); a3 = fmaf(t.w, w.w, a3);
        }
    }
    float acc = (a0 + a1) + (a2 + a3);

    // Block reduction: 6 warps
    #pragma unroll
    for (int o = 16; o > 0; o >>= 1)
        acc += __shfl_xor_sync(0xffffffffu, acc, o);

    __shared__ float s_warp[6];
    if ((tid & 31) == 0)
        s_warp[tid >> 5] = acc;
    __syncthreads();

    if (tid == 0) {
        float s = 0.0f;
        #pragma unroll
        for (int i = 0; i < 6; i++) s += s_warp[i];
        g_partial[blockIdx.x] = s;          // deterministic (no atomics)
    }
}

// ---------------------------------------------------------------------------
// Kernel 2: T_fb = sum of its SPLIT partials (fixed order), then
//           out = (1/F) * sum_fb T/(T+eps)
// ---------------------------------------------------------------------------
__global__ __launch_bounds__(128)
void noun_finish_kernel(float* __restrict__ out)
{
    const int tid = threadIdx.x;            // 0..127, one per (f,b)

    float t = 0.0f;
    #pragma unroll
    for (int i = 0; i < SPLIT; i++)
        t += g_partial[tid * SPLIT + i];

    float c = t / (t + EPSV);

    #pragma unroll
    for (int o = 16; o > 0; o >>= 1)
        c += __shfl_xor_sync(0xffffffffu, c, o);

    __shared__ float s_warp[4];
    if ((tid & 31) == 0)
        s_warp[tid >> 5] = c;
    __syncthreads();

    if (tid == 0)
        out[0] = (s_warp[0] + s_warp[1] + s_warp[2] + s_warp[3]) / (float)Fdim;
}

// ---------------------------------------------------------------------------
// Entry point. Inputs (metadata order):
//   d_in[0] token_embeddings  f32 [F,B,S,D]
//   d_in[1] sentence_embedding f32 [F,B,D]
//   d_in[2] attention_mask     i32 [F,B,S]
// d_out: 1 float scalar
// ---------------------------------------------------------------------------
extern "C" void kernel_launch(void* const* d_in, const int* in_sizes, int n_in,
                              void* d_out, int out_size)
{
    (void)in_sizes; (void)n_in; (void)out_size;
    const float4* tok  = (const float4*)d_in[0];
    const float4* sent = (const float4*)d_in[1];
    const int*    mask = (const int*)d_in[2];
    float*        out  = (float*)d_out;

    noun_dot_kernel<<<NBLK, 192>>>(tok, sent, mask);
    noun_finish_kernel<<<1, 128>>>(out);
}